// round 14
// baseline (speedup 1.0000x reference)
#include <cuda_runtime.h>
#include <cuda_bf16.h>
#include <cuda_fp16.h>
#include <cstdint>

#define NN 100000
#define EE 600000
#define RR 3
#define FIN 128
#define FOUT 64
#define M_ROWS (RR * NN)          // 300000

// ---------------- scratch (device globals; no allocation allowed) ----------
__device__ __half2 g_hwh[(size_t)RR * NN * (FOUT / 2)];  // x @ W per relation, fp16 (38.4 MB)
__device__ float g_dinv[M_ROWS];
__device__ int   g_cnt[M_ROWS];
__device__ int   g_cur[M_ROWS];
__device__ int   g_off[M_ROWS];
__device__ __align__(16) int4 g_csr_rec[RR * EE];  // per-edge {src, perm[src], w_bits, 0}
__device__ int   g_part[256];
// W bf16 split images, layout [img 6][n 64][kpair 68(pad)] words; img = rel*2 + (0=hi,1=lo)
__device__ __align__(16) uint32_t g_wimg[6 * 64 * 68];

__device__ __forceinline__ uint32_t bf16_split_pack(float a, float b, uint32_t& lo_pack) {
    __nv_bfloat16 ha = __float2bfloat16_rn(a);
    __nv_bfloat16 hb = __float2bfloat16_rn(b);
    __nv_bfloat16 la = __float2bfloat16_rn(a - __bfloat162float(ha));
    __nv_bfloat16 lb = __float2bfloat16_rn(b - __bfloat162float(hb));
    lo_pack = (uint32_t)__bfloat16_as_ushort(la) | ((uint32_t)__bfloat16_as_ushort(lb) << 16);
    return (uint32_t)__bfloat16_as_ushort(ha) | ((uint32_t)__bfloat16_as_ushort(hb) << 16);
}
__device__ __forceinline__ void mma_bf16(float* c, uint32_t a0, uint32_t a1, uint32_t a2, uint32_t a3,
                                         uint32_t b0, uint32_t b1) {
    asm volatile("mma.sync.aligned.m16n8k16.row.col.f32.bf16.bf16.f32 "
                 "{%0,%1,%2,%3}, {%4,%5,%6,%7}, {%8,%9}, {%0,%1,%2,%3};"
                 : "+f"(c[0]), "+f"(c[1]), "+f"(c[2]), "+f"(c[3])
                 : "r"(a0), "r"(a1), "r"(a2), "r"(a3), "r"(b0), "r"(b1));
}

// 0a) zero counts/cursors/summary (MAIN chain)
__global__ void k_zero(float* __restrict__ out_sum) {
    int i = blockIdx.x * blockDim.x + threadIdx.x;
    if (i < M_ROWS) { g_cnt[i] = 0; g_cur[i] = 0; }
    if (i < RR * FOUT) out_sum[i] = 0.0f;
}

// 0b) convert W into bf16 hi/lo images (SIDE chain)
__global__ void k_wconv(const float* __restrict__ Ws) {
    int i = blockIdx.x * blockDim.x + threadIdx.x;
    if (i >= RR * 64 * 64) return;                  // (r, n, kpair)
    int r = i >> 12, rem = i & 4095, n = rem >> 6, kp = rem & 63;
    const float* W = Ws + (size_t)r * FIN * FOUT;
    float w0 = W[(2 * kp) * FOUT + n];
    float w1 = W[(2 * kp + 1) * FOUT + n];
    uint32_t lp, hp = bf16_split_pack(w0, w1, lp);
    g_wimg[(r * 2 + 0) * (64 * 68) + n * 68 + kp] = hp;
    g_wimg[(r * 2 + 1) * (64 * 68) + n * 68 + kp] = lp;
}

// 1) count in-degrees over dst (int4 vectorized; EE % 4 == 0)
__global__ void k_count(const int* __restrict__ ei) {
    int i = blockIdx.x * blockDim.x + threadIdx.x;     // over RR*EE/4
    if (i >= RR * (EE / 4)) return;
    int r = i / (EE / 4), q = i - r * (EE / 4);
    int4 d4 = *(const int4*)(ei + (size_t)r * 2 * EE + EE + q * 4);
    atomicAdd(&g_cnt[r * NN + d4.x], 1);
    atomicAdd(&g_cnt[r * NN + d4.y], 1);
    atomicAdd(&g_cnt[r * NN + d4.z], 1);
    atomicAdd(&g_cnt[r * NN + d4.w], 1);
}

// 2) exclusive scan of g_cnt -> g_off (block-local) + fused dinv
#define SCAN_NB ((M_ROWS + 2047) / 2048)
__global__ void k_scan1() {
    __shared__ int sh[512];
    int b = blockIdx.x, tid = threadIdx.x;
    int base = b * 2048 + tid * 4;
    int v[4], s = 0;
#pragma unroll
    for (int j = 0; j < 4; j++) {
        int idx = base + j;
        v[j] = (idx < M_ROWS) ? g_cnt[idx] : 0;
        s += v[j];
        if (idx < M_ROWS) g_dinv[idx] = rsqrtf((float)(v[j] + 1));
    }
    sh[tid] = s; __syncthreads();
    for (int o = 1; o < 512; o <<= 1) {
        int t = (tid >= o) ? sh[tid - o] : 0;
        __syncthreads();
        sh[tid] += t;
        __syncthreads();
    }
    int run = sh[tid] - s;
#pragma unroll
    for (int j = 0; j < 4; j++) { int idx = base + j; if (idx < M_ROWS) g_off[idx] = run; run += v[j]; }
    if (tid == 511) g_part[b] = sh[511];
}

// 3) per-relation GEMM via mma.sync bf16 2-way split (R10 inner structure)
#define A_WORDS (128 * 68)            // 34816 B
#define B_WORDS (64 * 68)             // 17408 B
#define SM_AH 0
#define SM_AL (A_WORDS * 4)
#define SM_B  (2 * A_WORDS * 4)       // 69632
#define SMEM_MMA (SM_B + 2 * B_WORDS * 4)   // 104448
#define NB_TILES ((NN + 127) / 128)

__global__ void __launch_bounds__(256, 2) k_gemm_r(const float* __restrict__ x, int rel) {
    extern __shared__ char smem[];
    uint32_t* sAH = (uint32_t*)(smem + SM_AH);
    uint32_t* sAL = (uint32_t*)(smem + SM_AL);
    uint32_t* sB  = (uint32_t*)(smem + SM_B);

    const int tid = threadIdx.x;
    const int row0 = blockIdx.x * 128;
    const int nrows = min(128, NN - row0);

    // stage this relation's W images (hi, lo)
    {
        const uint4* src = (const uint4*)(g_wimg + rel * 2 * B_WORDS);
        uint4* dst = (uint4*)sB;
        for (int i = tid; i < 2 * B_WORDS / 4; i += 256) dst[i] = src[i];
    }
    // convert x tile -> A_hi / A_lo bf16 (zero-pad past nrows)
    for (int i = tid; i < 128 * 64; i += 256) {
        int row = i >> 6, kp = i & 63;
        float2 v = make_float2(0.f, 0.f);
        if (row < nrows) v = *(const float2*)(x + (size_t)(row0 + row) * FIN + kp * 2);
        uint32_t lp, hp = bf16_split_pack(v.x, v.y, lp);
        sAH[row * 68 + kp] = hp;
        sAL[row * 68 + kp] = lp;
    }
    __syncthreads();

    const int w = tid >> 5, lane = tid & 31;
    const int grp = lane >> 2, tig = lane & 3;
    const int rbase = w * 16;

    float acc[8][4];
#pragma unroll
    for (int nf = 0; nf < 8; nf++)
#pragma unroll
        for (int q = 0; q < 4; q++) acc[nf][q] = 0.0f;

    for (int prod = 0; prod < 3; prod++) {
        const uint32_t* aImg = (prod == 2) ? sAL : sAH;
        const uint32_t* bImg = sB + ((prod == 1) ? B_WORDS : 0);
#pragma unroll
        for (int ks = 0; ks < 8; ks++) {
            uint32_t b0[8], b1[8];
#pragma unroll
            for (int nf = 0; nf < 8; nf++) {
                int bw = (nf * 8 + grp) * 68 + ks * 8 + tig;
                b0[nf] = bImg[bw];
                b1[nf] = bImg[bw + 4];
            }
            int aw = (rbase + grp) * 68 + ks * 8 + tig;
            uint32_t a0 = aImg[aw];
            uint32_t a1 = aImg[aw + 8 * 68];
            uint32_t a2 = aImg[aw + 4];
            uint32_t a3 = aImg[aw + 8 * 68 + 4];
#pragma unroll
            for (int nf = 0; nf < 8; nf++)
                mma_bf16(acc[nf], a0, a1, a2, a3, b0[nf], b1[nf]);
        }
    }

    __half2* dstR = g_hwh + ((size_t)rel * NN + row0) * (FOUT / 2);
    int rr = rbase + grp;
#pragma unroll
    for (int nf = 0; nf < 8; nf++) {
        int hc = nf * 4 + tig;          // half2 column (covers cols 2hc, 2hc+1)
        if (rr < nrows)
            dstR[(size_t)rr * (FOUT / 2) + hc] = __floats2half2_rn(acc[nf][0], acc[nf][1]);
        if (rr + 8 < nrows)
            dstR[(size_t)(rr + 8) * (FOUT / 2) + hc] = __floats2half2_rn(acc[nf][2], acc[nf][3]);
    }
}

// 4) scan pass 2 (block partials)
__global__ void k_scan2(int n) {
    __shared__ int sh[256];
    int tid = threadIdx.x;
    int v = (tid < n) ? g_part[tid] : 0;
    sh[tid] = v; __syncthreads();
    for (int o = 1; o < 256; o <<= 1) {
        int t = (tid >= o) ? sh[tid - o] : 0;
        __syncthreads();
        sh[tid] += t;
        __syncthreads();
    }
    if (tid < n) g_part[tid] = sh[tid] - v;
}

// 5) fill CSR with fully-precomputed 16B edge records
__global__ void k_fill(const int* __restrict__ ei, const int* __restrict__ perms) {
    int i = blockIdx.x * blockDim.x + threadIdx.x;
    if (i >= RR * EE) return;
    int r = i / EE, e = i - r * EE;
    const int* base = ei + (size_t)r * 2 * EE;
    int s = base[e];
    int d = base[EE + e];
    int g = r * NN + d;
    int gs = r * NN + s;
    int p = g_off[g] + g_part[g >> 11] + atomicAdd(&g_cur[g], 1);
    float w = g_dinv[gs] * g_dinv[g];
    g_csr_rec[p] = make_int4(s, perms[gs], __float_as_int(w), 0);
}

// 6) per-relation fused gather (R10-proven inner loop)
#define GB 1024
__global__ void __launch_bounds__(256) k_gather_r(int r,
                                                  const int* __restrict__ perms,
                                                  const float* __restrict__ bs,
                                                  float* __restrict__ out_pos,
                                                  float* __restrict__ out_neg,
                                                  float* __restrict__ out_sum) {
    __shared__ float ssum[FOUT];
    const int tid = threadIdx.x;
    if (tid < FOUT) ssum[tid] = 0.0f;
    __syncthreads();

    const int wid = tid >> 5, lane = tid & 31;
    const int half = lane >> 4, l = lane & 15;
    const __half2* hwr = g_hwh + (size_t)r * NN * (FOUT / 2);
    float* outb = half ? out_neg : out_pos;
    const float4 b4 = *(const float4*)(bs + r * FOUT + l * 4);

    float4 asum = make_float4(0.f, 0.f, 0.f, 0.f);

    for (int row = blockIdx.x * 8 + wid; row < NN; row += GB * 8) {
        int g = r * NN + row;
        float dd = g_dinv[g];
        int self_s = half ? perms[g] : row;
        uint2 raw = *(const uint2*)(hwr + (size_t)self_s * (FOUT / 2) + l * 2);
        float2 f0 = __half22float2(*(__half2*)&raw.x);
        float2 f1 = __half22float2(*(__half2*)&raw.y);
        float w0 = dd * dd;
        float4 acc = make_float4(f0.x * w0, f0.y * w0, f1.x * w0, f1.y * w0);

        int beg = g_off[g] + g_part[g >> 11];
        int end = beg + g_cnt[g];
        int e = beg;
        for (; e + 4 <= end; e += 4) {
            int4 rec[4];
#pragma unroll
            for (int j = 0; j < 4; j++) rec[j] = g_csr_rec[e + j];
            uint2 u[4];
#pragma unroll
            for (int j = 0; j < 4; j++) {
                int s2 = half ? rec[j].y : rec[j].x;
                u[j] = *(const uint2*)(hwr + (size_t)s2 * (FOUT / 2) + l * 2);
            }
#pragma unroll
            for (int j = 0; j < 4; j++) {
                float ww = __int_as_float(rec[j].z);
                float2 u0 = __half22float2(*(__half2*)&u[j].x);
                float2 u1 = __half22float2(*(__half2*)&u[j].y);
                acc.x += u0.x * ww; acc.y += u0.y * ww;
                acc.z += u1.x * ww; acc.w += u1.y * ww;
            }
        }
        for (; e < end; e++) {
            int4 rec = g_csr_rec[e];
            float ww = __int_as_float(rec.z);
            int s2 = half ? rec.y : rec.x;
            uint2 u = *(const uint2*)(hwr + (size_t)s2 * (FOUT / 2) + l * 2);
            float2 u0 = __half22float2(*(__half2*)&u.x);
            float2 u1 = __half22float2(*(__half2*)&u.y);
            acc.x += u0.x * ww; acc.y += u0.y * ww;
            acc.z += u1.x * ww; acc.w += u1.y * ww;
        }
        acc.x = fmaxf(acc.x + b4.x, 0.0f);
        acc.y = fmaxf(acc.y + b4.y, 0.0f);
        acc.z = fmaxf(acc.z + b4.z, 0.0f);
        acc.w = fmaxf(acc.w + b4.w, 0.0f);
        *(float4*)(outb + (size_t)g * FOUT + l * 4) = acc;
        if (!half) {
            asum.x += acc.x; asum.y += acc.y; asum.z += acc.z; asum.w += acc.w;
        }
    }
    if (!half) {
        atomicAdd(&ssum[l * 4 + 0], asum.x);
        atomicAdd(&ssum[l * 4 + 1], asum.y);
        atomicAdd(&ssum[l * 4 + 2], asum.z);
        atomicAdd(&ssum[l * 4 + 3], asum.w);
    }
    __syncthreads();
    if (tid < FOUT) atomicAdd(&out_sum[r * FOUT + tid], ssum[tid]);
}

// 7) summaries /= N
__global__ void k_scale(float* __restrict__ out_sum) {
    int i = threadIdx.x;
    if (i < RR * FOUT) out_sum[i] *= (1.0f / NN);
}

// ---------------- launch: per-relation gemm/gather pipeline ----------------
extern "C" void kernel_launch(void* const* d_in, const int* in_sizes, int n_in,
                              void* d_out, int out_size) {
    const float* x     = (const float*)d_in[0];
    const int*   ei    = (const int*)d_in[1];
    const int*   perms = (const int*)d_in[2];
    const float* Ws    = (const float*)d_in[3];
    const float* bs    = (const float*)d_in[4];

    float* out = (float*)d_out;
    float* out_pos = out;
    float* out_neg = out + (size_t)RR * NN * FOUT;
    float* out_sum = out + (size_t)2 * RR * NN * FOUT;

    cudaFuncSetAttribute(k_gemm_r, cudaFuncAttributeMaxDynamicSharedMemorySize, SMEM_MMA);

    cudaStream_t s2;
    cudaEvent_t ev_fork, ev_g[RR];
    cudaStreamCreateWithFlags(&s2, cudaStreamNonBlocking);
    cudaEventCreateWithFlags(&ev_fork, cudaEventDisableTiming);
    for (int r = 0; r < RR; r++) cudaEventCreateWithFlags(&ev_g[r], cudaEventDisableTiming);

    // fork
    cudaEventRecord(ev_fork, 0);
    cudaStreamWaitEvent(s2, ev_fork, 0);

    // SIDE chain: W conversion -> per-relation GEMMs, each signaling an event
    k_wconv<<<(RR * 64 * 64 + 255) / 256, 256, 0, s2>>>(Ws);
    for (int r = 0; r < RR; r++) {
        k_gemm_r<<<NB_TILES, 256, SMEM_MMA, s2>>>(x, r);
        cudaEventRecord(ev_g[r], s2);
    }

    // MAIN chain: CSR build
    k_zero<<<(M_ROWS + 255) / 256, 256>>>(out_sum);
    k_count<<<(RR * (EE / 4) + 255) / 256, 256>>>(ei);
    k_scan1<<<SCAN_NB, 512>>>();
    k_scan2<<<1, 256>>>(SCAN_NB);
    k_fill<<<(RR * EE + 255) / 256, 256>>>(ei, perms);

    // per-relation gathers: each waits only on its gemm (CSR done on this stream)
    for (int r = 0; r < RR; r++) {
        cudaStreamWaitEvent(0, ev_g[r], 0);
        k_gather_r<<<GB, 256>>>(r, perms, bs, out_pos, out_neg, out_sum);
    }
    k_scale<<<1, 256>>>(out_sum);
}

// round 15
// speedup vs baseline: 1.5062x; 1.5062x over previous
#include <cuda_runtime.h>
#include <cuda_bf16.h>
#include <cuda_fp16.h>
#include <cstdint>

#define NN 100000
#define EE 600000
#define RR 3
#define FIN 128
#define FOUT 64
#define M_ROWS (RR * NN)          // 300000

// ---------------- scratch (device globals; no allocation allowed) ----------
__device__ __half2 g_hwh[(size_t)RR * NN * (FOUT / 2)];  // x @ W per relation, fp16 (38.4 MB)
__device__ float g_dinv[M_ROWS];
__device__ int   g_cnt[M_ROWS];
__device__ int   g_off[M_ROWS];   // block-local excl scan; consumed (incremented) by k_fill
__device__ __align__(16) int4 g_csr_rec[RR * EE];  // per-edge {src, perm[src], w_bits, 0}
__device__ int   g_part[256];
// W bf16 split images, layout [img 6][n 64][kpair 68(pad)] words; img = rel*2 + (0=hi,1=lo)
__device__ __align__(16) uint32_t g_wimg[6 * 64 * 68];

__device__ __forceinline__ uint32_t bf16_split_pack(float a, float b, uint32_t& lo_pack) {
    __nv_bfloat16 ha = __float2bfloat16_rn(a);
    __nv_bfloat16 hb = __float2bfloat16_rn(b);
    __nv_bfloat16 la = __float2bfloat16_rn(a - __bfloat162float(ha));
    __nv_bfloat16 lb = __float2bfloat16_rn(b - __bfloat162float(hb));
    lo_pack = (uint32_t)__bfloat16_as_ushort(la) | ((uint32_t)__bfloat16_as_ushort(lb) << 16);
    return (uint32_t)__bfloat16_as_ushort(ha) | ((uint32_t)__bfloat16_as_ushort(hb) << 16);
}
__device__ __forceinline__ void mma_bf16(float* c, uint32_t a0, uint32_t a1, uint32_t a2, uint32_t a3,
                                         uint32_t b0, uint32_t b1) {
    asm volatile("mma.sync.aligned.m16n8k16.row.col.f32.bf16.bf16.f32 "
                 "{%0,%1,%2,%3}, {%4,%5,%6,%7}, {%8,%9}, {%0,%1,%2,%3};"
                 : "+f"(c[0]), "+f"(c[1]), "+f"(c[2]), "+f"(c[3])
                 : "r"(a0), "r"(a1), "r"(a2), "r"(a3), "r"(b0), "r"(b1));
}

// 0a) zero counts/summary (MAIN chain)
__global__ void k_zero(float* __restrict__ out_sum) {
    int i = blockIdx.x * blockDim.x + threadIdx.x;
    if (i < M_ROWS) g_cnt[i] = 0;
    if (i < RR * FOUT) out_sum[i] = 0.0f;
}

// 0b) convert W into bf16 hi/lo images (SIDE chain)
__global__ void k_wconv(const float* __restrict__ Ws) {
    int i = blockIdx.x * blockDim.x + threadIdx.x;
    if (i >= RR * 64 * 64) return;                  // (r, n, kpair)
    int r = i >> 12, rem = i & 4095, n = rem >> 6, kp = rem & 63;
    const float* W = Ws + (size_t)r * FIN * FOUT;
    float w0 = W[(2 * kp) * FOUT + n];
    float w1 = W[(2 * kp + 1) * FOUT + n];
    uint32_t lp, hp = bf16_split_pack(w0, w1, lp);
    g_wimg[(r * 2 + 0) * (64 * 68) + n * 68 + kp] = hp;
    g_wimg[(r * 2 + 1) * (64 * 68) + n * 68 + kp] = lp;
}

// 1) count in-degrees over dst (int4 vectorized; EE % 4 == 0)
__global__ void k_count(const int* __restrict__ ei) {
    int i = blockIdx.x * blockDim.x + threadIdx.x;     // over RR*EE/4
    if (i >= RR * (EE / 4)) return;
    int r = i / (EE / 4), q = i - r * (EE / 4);
    int4 d4 = *(const int4*)(ei + (size_t)r * 2 * EE + EE + q * 4);
    atomicAdd(&g_cnt[r * NN + d4.x], 1);
    atomicAdd(&g_cnt[r * NN + d4.y], 1);
    atomicAdd(&g_cnt[r * NN + d4.z], 1);
    atomicAdd(&g_cnt[r * NN + d4.w], 1);
}

// 2) exclusive scan of g_cnt -> g_off (block-local) + fused dinv
#define SCAN_NB ((M_ROWS + 2047) / 2048)
__global__ void k_scan1() {
    __shared__ int sh[512];
    int b = blockIdx.x, tid = threadIdx.x;
    int base = b * 2048 + tid * 4;
    int v[4], s = 0;
#pragma unroll
    for (int j = 0; j < 4; j++) {
        int idx = base + j;
        v[j] = (idx < M_ROWS) ? g_cnt[idx] : 0;
        s += v[j];
        if (idx < M_ROWS) g_dinv[idx] = rsqrtf((float)(v[j] + 1));
    }
    sh[tid] = s; __syncthreads();
    for (int o = 1; o < 512; o <<= 1) {
        int t = (tid >= o) ? sh[tid - o] : 0;
        __syncthreads();
        sh[tid] += t;
        __syncthreads();
    }
    int run = sh[tid] - s;
#pragma unroll
    for (int j = 0; j < 4; j++) { int idx = base + j; if (idx < M_ROWS) g_off[idx] = run; run += v[j]; }
    if (tid == 511) g_part[b] = sh[511];
}

// 3) GEMM via mma.sync bf16 2-way split (R10-proven form; SIDE stream)
#define A_WORDS (128 * 68)            // 34816 B
#define B_WORDS (64 * 68)             // 17408 B
#define SM_AH 0
#define SM_AL (A_WORDS * 4)
#define SM_B  (2 * A_WORDS * 4)       // 69632
#define SMEM_MMA (SM_B + 2 * B_WORDS * 4)   // 104448
#define NB_TILES ((NN + 127) / 128)

__global__ void __launch_bounds__(256, 2) k_gemm_mma(const float* __restrict__ x) {
    extern __shared__ char smem[];
    uint32_t* sAH = (uint32_t*)(smem + SM_AH);
    uint32_t* sAL = (uint32_t*)(smem + SM_AL);
    uint32_t* sB  = (uint32_t*)(smem + SM_B);

    const int tid = threadIdx.x;
    const int row0 = blockIdx.x * 128;
    const int nrows = min(128, NN - row0);

    // convert x tile -> A_hi / A_lo bf16 (zero-pad past nrows)
    for (int i = tid; i < 128 * 64; i += 256) {
        int row = i >> 6, kp = i & 63;
        float2 v = make_float2(0.f, 0.f);
        if (row < nrows) v = *(const float2*)(x + (size_t)(row0 + row) * FIN + kp * 2);
        uint32_t lp, hp = bf16_split_pack(v.x, v.y, lp);
        sAH[row * 68 + kp] = hp;
        sAL[row * 68 + kp] = lp;
    }

    const int w = tid >> 5, lane = tid & 31;
    const int grp = lane >> 2, tig = lane & 3;
    const int rbase = w * 16;

    for (int rel = 0; rel < RR; rel++) {
        if (rel > 0) __syncthreads();    // prior readers done with sB
        {
            const uint4* src = (const uint4*)(g_wimg + rel * 2 * B_WORDS);
            uint4* dst = (uint4*)sB;
            for (int i = tid; i < 2 * B_WORDS / 4; i += 256) dst[i] = src[i];
        }
        __syncthreads();

        float acc[8][4];
#pragma unroll
        for (int nf = 0; nf < 8; nf++)
#pragma unroll
            for (int q = 0; q < 4; q++) acc[nf][q] = 0.0f;

        for (int prod = 0; prod < 3; prod++) {
            const uint32_t* aImg = (prod == 2) ? sAL : sAH;
            const uint32_t* bImg = sB + ((prod == 1) ? B_WORDS : 0);
#pragma unroll
            for (int ks = 0; ks < 8; ks++) {
                uint32_t b0[8], b1[8];
#pragma unroll
                for (int nf = 0; nf < 8; nf++) {
                    int bw = (nf * 8 + grp) * 68 + ks * 8 + tig;
                    b0[nf] = bImg[bw];
                    b1[nf] = bImg[bw + 4];
                }
                int aw = (rbase + grp) * 68 + ks * 8 + tig;
                uint32_t a0 = aImg[aw];
                uint32_t a1 = aImg[aw + 8 * 68];
                uint32_t a2 = aImg[aw + 4];
                uint32_t a3 = aImg[aw + 8 * 68 + 4];
#pragma unroll
                for (int nf = 0; nf < 8; nf++)
                    mma_bf16(acc[nf], a0, a1, a2, a3, b0[nf], b1[nf]);
            }
        }

        __half2* dstR = g_hwh + ((size_t)rel * NN + row0) * (FOUT / 2);
        int rr = rbase + grp;
#pragma unroll
        for (int nf = 0; nf < 8; nf++) {
            int hc = nf * 4 + tig;          // half2 column (covers cols 2hc, 2hc+1)
            if (rr < nrows)
                dstR[(size_t)rr * (FOUT / 2) + hc] = __floats2half2_rn(acc[nf][0], acc[nf][1]);
            if (rr + 8 < nrows)
                dstR[(size_t)(rr + 8) * (FOUT / 2) + hc] = __floats2half2_rn(acc[nf][2], acc[nf][3]);
        }
    }
}

// 4) scan pass 2 (block partials)
__global__ void k_scan2(int n) {
    __shared__ int sh[256];
    int tid = threadIdx.x;
    int v = (tid < n) ? g_part[tid] : 0;
    sh[tid] = v; __syncthreads();
    for (int o = 1; o < 256; o <<= 1) {
        int t = (tid >= o) ? sh[tid - o] : 0;
        __syncthreads();
        sh[tid] += t;
        __syncthreads();
    }
    if (tid < n) g_part[tid] = sh[tid] - v;
}

// 5) fill CSR: single atomic per edge, consuming g_off (post: g_off[g] = local_off + cnt[g])
__global__ void k_fill(const int* __restrict__ ei, const int* __restrict__ perms) {
    int i = blockIdx.x * blockDim.x + threadIdx.x;
    if (i >= RR * EE) return;
    int r = i / EE, e = i - r * EE;
    const int* base = ei + (size_t)r * 2 * EE;
    int s = base[e];
    int d = base[EE + e];
    int g = r * NN + d;
    int gs = r * NN + s;
    int p = atomicAdd(&g_off[g], 1) + g_part[g >> 11];
    float w = g_dinv[gs] * g_dinv[g];
    g_csr_rec[p] = make_int4(s, perms[gs], __float_as_int(w), 0);
}

// 6) fused gather (R10-proven form): end = g_off[g]+part (post-fill), beg = end - cnt
#define GB 1024
__global__ void __launch_bounds__(256) k_gather(const int* __restrict__ perms,
                                                const float* __restrict__ bs,
                                                float* __restrict__ out_pos,
                                                float* __restrict__ out_neg,
                                                float* __restrict__ out_sum) {
    __shared__ float ssum[FOUT];
    const int r = blockIdx.y;
    const int tid = threadIdx.x;
    if (tid < FOUT) ssum[tid] = 0.0f;
    __syncthreads();

    const int wid = tid >> 5, lane = tid & 31;
    const int half = lane >> 4, l = lane & 15;
    const __half2* hwr = g_hwh + (size_t)r * NN * (FOUT / 2);
    float* outb = half ? out_neg : out_pos;
    const float4 b4 = *(const float4*)(bs + r * FOUT + l * 4);

    float4 asum = make_float4(0.f, 0.f, 0.f, 0.f);

    for (int row = blockIdx.x * 8 + wid; row < NN; row += GB * 8) {
        int g = r * NN + row;
        float dd = g_dinv[g];
        int self_s = half ? perms[g] : row;
        uint2 raw = *(const uint2*)(hwr + (size_t)self_s * (FOUT / 2) + l * 2);
        float2 f0 = __half22float2(*(__half2*)&raw.x);
        float2 f1 = __half22float2(*(__half2*)&raw.y);
        float w0 = dd * dd;
        float4 acc = make_float4(f0.x * w0, f0.y * w0, f1.x * w0, f1.y * w0);

        int end = g_off[g] + g_part[g >> 11];   // g_off consumed by fill: local_off + cnt
        int beg = end - g_cnt[g];
        int e = beg;
        for (; e + 4 <= end; e += 4) {
            int4 rec[4];
#pragma unroll
            for (int j = 0; j < 4; j++) rec[j] = g_csr_rec[e + j];
            uint2 u[4];
#pragma unroll
            for (int j = 0; j < 4; j++) {
                int s2 = half ? rec[j].y : rec[j].x;
                u[j] = *(const uint2*)(hwr + (size_t)s2 * (FOUT / 2) + l * 2);
            }
#pragma unroll
            for (int j = 0; j < 4; j++) {
                float ww = __int_as_float(rec[j].z);
                float2 u0 = __half22float2(*(__half2*)&u[j].x);
                float2 u1 = __half22float2(*(__half2*)&u[j].y);
                acc.x += u0.x * ww; acc.y += u0.y * ww;
                acc.z += u1.x * ww; acc.w += u1.y * ww;
            }
        }
        for (; e < end; e++) {
            int4 rec = g_csr_rec[e];
            float ww = __int_as_float(rec.z);
            int s2 = half ? rec.y : rec.x;
            uint2 u = *(const uint2*)(hwr + (size_t)s2 * (FOUT / 2) + l * 2);
            float2 u0 = __half22float2(*(__half2*)&u.x);
            float2 u1 = __half22float2(*(__half2*)&u.y);
            acc.x += u0.x * ww; acc.y += u0.y * ww;
            acc.z += u1.x * ww; acc.w += u1.y * ww;
        }
        acc.x = fmaxf(acc.x + b4.x, 0.0f);
        acc.y = fmaxf(acc.y + b4.y, 0.0f);
        acc.z = fmaxf(acc.z + b4.z, 0.0f);
        acc.w = fmaxf(acc.w + b4.w, 0.0f);
        *(float4*)(outb + (size_t)g * FOUT + l * 4) = acc;
        if (!half) {
            asum.x += acc.x; asum.y += acc.y; asum.z += acc.z; asum.w += acc.w;
        }
    }
    if (!half) {
        atomicAdd(&ssum[l * 4 + 0], asum.x);
        atomicAdd(&ssum[l * 4 + 1], asum.y);
        atomicAdd(&ssum[l * 4 + 2], asum.z);
        atomicAdd(&ssum[l * 4 + 3], asum.w);
    }
    __syncthreads();
    if (tid < FOUT) atomicAdd(&out_sum[r * FOUT + tid], ssum[tid]);
}

// 7) summaries /= N
__global__ void k_scale(float* __restrict__ out_sum) {
    int i = threadIdx.x;
    if (i < RR * FOUT) out_sum[i] *= (1.0f / NN);
}

// ---------------- launch: fork-join overlap of CSR build and GEMM ----------
extern "C" void kernel_launch(void* const* d_in, const int* in_sizes, int n_in,
                              void* d_out, int out_size) {
    const float* x     = (const float*)d_in[0];
    const int*   ei    = (const int*)d_in[1];
    const int*   perms = (const int*)d_in[2];
    const float* Ws    = (const float*)d_in[3];
    const float* bs    = (const float*)d_in[4];

    float* out = (float*)d_out;
    float* out_pos = out;
    float* out_neg = out + (size_t)RR * NN * FOUT;
    float* out_sum = out + (size_t)2 * RR * NN * FOUT;

    cudaFuncSetAttribute(k_gemm_mma, cudaFuncAttributeMaxDynamicSharedMemorySize, SMEM_MMA);

    cudaStream_t s2;
    cudaEvent_t ev_fork, ev_gemm;
    cudaStreamCreateWithFlags(&s2, cudaStreamNonBlocking);
    cudaEventCreateWithFlags(&ev_fork, cudaEventDisableTiming);
    cudaEventCreateWithFlags(&ev_gemm, cudaEventDisableTiming);

    // fork
    cudaEventRecord(ev_fork, 0);
    cudaStreamWaitEvent(s2, ev_fork, 0);

    // SIDE chain: W conversion -> GEMM (independent of CSR build)
    k_wconv<<<(RR * 64 * 64 + 255) / 256, 256, 0, s2>>>(Ws);
    k_gemm_mma<<<NB_TILES, 256, SMEM_MMA, s2>>>(x);
    cudaEventRecord(ev_gemm, s2);

    // MAIN chain: CSR build
    k_zero<<<(M_ROWS + 255) / 256, 256>>>(out_sum);
    k_count<<<(RR * (EE / 4) + 255) / 256, 256>>>(ei);
    k_scan1<<<SCAN_NB, 512>>>();
    k_scan2<<<1, 256>>>(SCAN_NB);
    k_fill<<<(RR * EE + 255) / 256, 256>>>(ei, perms);

    // join: gather needs both chains
    cudaStreamWaitEvent(0, ev_gemm, 0);
    k_gather<<<dim3(GB, RR), 256>>>(perms, bs, out_pos, out_neg, out_sum);
    k_scale<<<1, 256>>>(out_sum);
}